// round 12
// baseline (speedup 1.0000x reference)
#include <cuda_runtime.h>
#include <cuda_bf16.h>
#include <cstdint>

// B = 8192 rows, T = 4096 features, G = 64 groups.
// Group sizes cycle (32, 64, 96, 64) x 16; boundaries all multiples of 32 ->
// each aligned 32-elem chunk belongs to one group (128 chunks/row).
// Output: d_out[0..B) = Z (fp32), d_out[B..B+B*64) = a (fp32 row-major [B,64]).
//
// R12: persistent DOUBLE-BUFFERED TMA pipeline (fixes R11's exposed copy lat).
//  - 888 persistent CTAs (6/SM), ~9 rows each, 2 x 16KB smem tiles
//  - row n+1's bulk copy is in flight while row n is reduced; tile reissued
//    for row n+2 right after the barrier that proves all reads completed
//  - loads cost zero registers and zero per-thread issue slots
//  - one __syncthreads per row (also the tile-reuse fence); R6 epilogue

#define T_DIM    4096
#define G_DIM    64
#define NTHREADS 256
#define GRID     888          // 6 CTAs/SM * 148 SMs

__device__ __forceinline__ uint32_t smem_u32(const void* p) {
    return (uint32_t)__cvta_generic_to_shared(p);
}

__device__ __forceinline__ void mbar_wait(uint32_t mbar_a, uint32_t parity) {
    uint32_t done;
    asm volatile(
        "{\n\t.reg .pred p;\n\t"
        "mbarrier.try_wait.parity.acquire.cta.shared::cta.b64 p, [%1], %2;\n\t"
        "selp.b32 %0, 1, 0, p;\n\t}"
        : "=r"(done) : "r"(mbar_a), "r"(parity) : "memory");
    if (!done) {
        asm volatile(
            "{\n\t.reg .pred P1;\n\t"
            "W_%=:\n\t"
            "mbarrier.try_wait.parity.acquire.cta.shared::cta.b64 P1, [%0], %1, 0x989680;\n\t"
            "@P1 bra.uni D_%=;\n\t"
            "bra.uni W_%=;\n\t"
            "D_%=:\n\t}"
            :: "r"(mbar_a), "r"(parity) : "memory");
    }
}

__device__ __forceinline__ void tma_row(uint32_t dst, const float* src, uint32_t mbar_a) {
    asm volatile("mbarrier.arrive.expect_tx.shared.b64 _, [%0], %1;"
                 :: "r"(mbar_a), "r"((uint32_t)(T_DIM * 4)) : "memory");
    asm volatile("cp.async.bulk.shared::cta.global.mbarrier::complete_tx::bytes "
                 "[%0], [%1], %2, [%3];"
                 :: "r"(dst), "l"(src), "r"((uint32_t)(T_DIM * 4)), "r"(mbar_a)
                 : "memory");
}

__global__ __launch_bounds__(NTHREADS)
void agp_kernel(const float* __restrict__ H,
                const float* __restrict__ score_w,
                const float* __restrict__ score_b,
                float* __restrict__ out, int B)
{
    const int tid = threadIdx.x;
    const int bid = blockIdx.x;

    __shared__ alignas(128) float tile[2][T_DIM];     // 2 x 16KB
    __shared__ float chunk_sum[2][T_DIM / 32];
    __shared__ alignas(8) uint64_t mbar[2];

    const uint32_t mb0 = smem_u32(&mbar[0]);
    const uint32_t mb1 = smem_u32(&mbar[1]);

    if (tid == 0) {
        asm volatile("mbarrier.init.shared.b64 [%0], 1;" :: "r"(mb0) : "memory");
        asm volatile("mbarrier.init.shared.b64 [%0], 1;" :: "r"(mb1) : "memory");
    }
    __syncthreads();

    // prologue: issue rows bid, bid+GRID into tiles 0, 1
    if (tid == 0) {
        if (bid < B)        tma_row(smem_u32(&tile[0][0]), H + (size_t)bid * T_DIM, mb0);
        if (bid + GRID < B) tma_row(smem_u32(&tile[1][0]), H + (size_t)(bid + GRID) * T_DIM, mb1);
    }

    const int   c_start[4] = {0, 1, 3, 6};
    const int   c_cnt[4]   = {1, 2, 3, 2};
    const float inv_sz[4]  = {1.0f/32.0f, 1.0f/64.0f, 1.0f/96.0f, 1.0f/64.0f};

    uint32_t ph0 = 0, ph1 = 0;
    int it = 0;
    #pragma unroll 1
    for (int r = bid; r < B; r += GRID, ++it) {
        const int s = it & 1;

        // wait for this tile's copy (usually already complete at steady state)
        if (s == 0) { mbar_wait(mb0, ph0); ph0 ^= 1; }
        else        { mbar_wait(mb1, ph1); ph1 ^= 1; }

        // ---- reduce tile[s] -> chunk_sum[s] (conflict-free LDS.128) ----
        const float4* t4 = reinterpret_cast<const float4*>(&tile[s][0]);
        #pragma unroll
        for (int k = 0; k < 4; ++k) {
            float4 v = t4[tid + NTHREADS * k];
            float sm = (v.x + v.y) + (v.z + v.w);
            sm += __shfl_xor_sync(0xffffffffu, sm, 1);
            sm += __shfl_xor_sync(0xffffffffu, sm, 2);
            sm += __shfl_xor_sync(0xffffffffu, sm, 4);
            if ((tid & 7) == 0)
                chunk_sum[s][(tid >> 3) + 32 * k] = sm;
        }
        __syncthreads();   // chunk_sum visible; all reads of tile[s] complete

        // reissue this tile for row r + 2*GRID (safe after the barrier)
        if (tid == 0) {
            int rn = r + 2 * GRID;
            if (rn < B)
                tma_row(smem_u32(&tile[s][0]), H + (size_t)rn * T_DIM, s == 0 ? mb0 : mb1);
        }

        // ---- warp 0: groups -> softmax -> Z for row r (R6 epilogue) ----
        if (tid < 32) {
            const float w    = __ldg(score_w);
            const float bias = __ldg(score_b);

            float Gm[2], sc[2];
            #pragma unroll
            for (int j = 0; j < 2; ++j) {
                int g    = tid + 32 * j;
                int sub  = g & 3;
                int base = (g >> 2) * 8 + c_start[sub];
                float acc = 0.0f;
                #pragma unroll
                for (int c = 0; c < 3; ++c)
                    if (c < c_cnt[sub]) acc += chunk_sum[s][base + c];
                Gm[j] = acc * inv_sz[sub];
                sc[j] = Gm[j] * w + bias;
            }

            float mx = fmaxf(sc[0], sc[1]);
            #pragma unroll
            for (int d = 16; d > 0; d >>= 1)
                mx = fmaxf(mx, __shfl_xor_sync(0xffffffffu, mx, d));

            float p0 = __expf(sc[0] - mx);
            float p1 = __expf(sc[1] - mx);

            float ssum = p0 + p1;
            float pz   = p0 * Gm[0] + p1 * Gm[1];
            #pragma unroll
            for (int d = 16; d > 0; d >>= 1) {
                ssum += __shfl_xor_sync(0xffffffffu, ssum, d);
                pz   += __shfl_xor_sync(0xffffffffu, pz, d);
            }
            float inv = 1.0f / ssum;

            float* a_out = out + B + (size_t)r * G_DIM;
            a_out[tid]      = p0 * inv;
            a_out[tid + 32] = p1 * inv;
            if (tid == 0) out[r] = pz * inv;   // Z = pz / ssum
        }
        // chunk_sum[s] is rewritten only at it+2, after the it+1 barrier that
        // warp 0 reaches post-epilogue -> no extra barrier needed.
    }
}

extern "C" void kernel_launch(void* const* d_in, const int* in_sizes, int n_in,
                              void* d_out, int out_size)
{
    const float* H  = (const float*)d_in[0];   // [B, 4096]
    const float* sw = (const float*)d_in[1];   // [1,1]
    const float* sb = (const float*)d_in[2];   // [1]
    float* out = (float*)d_out;

    int B = in_sizes[0] / T_DIM;               // 8192
    agp_kernel<<<GRID, NTHREADS>>>(H, sw, sb, out, B);
}

// round 13
// speedup vs baseline: 1.2315x; 1.2315x over previous
#include <cuda_runtime.h>
#include <cuda_bf16.h>

// B = 8192 rows, T = 4096 features, G = 64 groups.
// Group sizes cycle (32, 64, 96, 64) x 16; all boundaries are multiples of 32,
// so each aligned 32-elem chunk belongs to exactly one group (128 chunks/row).
// Output: d_out[0..B) = Z (fp32), d_out[B..B+B*64) = a (fp32 row-major [B,64]).
//
// R13 = convergence: R1's exact launch/load configuration (highest measured
// occ 86.2% / DRAM 74.9%: 256 thr, 1 row/CTA, grid 8192, plain launch bounds,
// smem-broadcast scalars) + R6's leaner epilogue (__expf, interleaved
// ssum/pz trees, Z = pz/ssum). 12 structural variants (multi-row, cp.async,
// split kernels, warp-per-row, TMA single & pipelined) all measured slower:
// this shape is the streaming ceiling for this pattern on sm_103a.

#define T_DIM    4096
#define G_DIM    64
#define NTHREADS 256

__global__ __launch_bounds__(NTHREADS)
void agp_kernel(const float* __restrict__ H,
                const float* __restrict__ score_w,
                const float* __restrict__ score_b,
                float* __restrict__ out, int B)
{
    const int b   = blockIdx.x;
    const int tid = threadIdx.x;

    __shared__ float chunk_sum[T_DIM / 32];   // 128 chunk sums
    __shared__ float s_w, s_b;
    if (tid == 0) { s_w = score_w[0]; s_b = score_b[0]; }

    const float4* row4 = reinterpret_cast<const float4*>(H + (size_t)b * T_DIM);

    // --- Phase 1: 4 coalesced LDG.128 per thread, butterfly to chunk sums ---
    #pragma unroll
    for (int k = 0; k < 4; ++k) {
        float4 v = row4[tid + NTHREADS * k];
        float s = (v.x + v.y) + (v.z + v.w);
        // aligned 8-lane butterfly -> one 32-elem chunk sum
        s += __shfl_xor_sync(0xffffffffu, s, 1);
        s += __shfl_xor_sync(0xffffffffu, s, 2);
        s += __shfl_xor_sync(0xffffffffu, s, 4);
        if ((tid & 7) == 0)
            chunk_sum[(tid >> 3) + 32 * k] = s;
    }
    __syncthreads();

    // --- Phase 2: warp 0 does groups -> softmax -> Z ---
    if (tid < 32) {
        const float w = s_w, bias = s_b;

        // per-subgroup (g & 3): chunk start within 8-chunk cycle, count, 1/size
        const int   c_start[4] = {0, 1, 3, 6};
        const int   c_cnt[4]   = {1, 2, 3, 2};
        const float inv_sz[4]  = {1.0f/32.0f, 1.0f/64.0f, 1.0f/96.0f, 1.0f/64.0f};

        float Gm[2], sc[2];
        #pragma unroll
        for (int j = 0; j < 2; ++j) {
            int g    = tid + 32 * j;
            int sub  = g & 3;
            int base = (g >> 2) * 8 + c_start[sub];
            float s = 0.0f;
            #pragma unroll
            for (int c = 0; c < 3; ++c)
                if (c < c_cnt[sub]) s += chunk_sum[base + c];
            Gm[j] = s * inv_sz[sub];
            sc[j] = Gm[j] * w + bias;
        }

        // max tree (required before exp)
        float mx = fmaxf(sc[0], sc[1]);
        #pragma unroll
        for (int d = 16; d > 0; d >>= 1)
            mx = fmaxf(mx, __shfl_xor_sync(0xffffffffu, mx, d));

        float p0 = __expf(sc[0] - mx);
        float p1 = __expf(sc[1] - mx);

        // interleaved independent trees: ssum = sum(p), pz = sum(p*G)
        float ssum = p0 + p1;
        float pz   = p0 * Gm[0] + p1 * Gm[1];
        #pragma unroll
        for (int d = 16; d > 0; d >>= 1) {
            ssum += __shfl_xor_sync(0xffffffffu, ssum, d);
            pz   += __shfl_xor_sync(0xffffffffu, pz, d);
        }
        float inv = 1.0f / ssum;

        float* a_out = out + B + (size_t)b * G_DIM;
        a_out[tid]      = p0 * inv;
        a_out[tid + 32] = p1 * inv;
        if (tid == 0) out[b] = pz * inv;   // Z = sum(a*G) = pz / ssum
    }
}

extern "C" void kernel_launch(void* const* d_in, const int* in_sizes, int n_in,
                              void* d_out, int out_size)
{
    const float* H  = (const float*)d_in[0];   // [B, 4096]
    const float* sw = (const float*)d_in[1];   // [1,1]
    const float* sb = (const float*)d_in[2];   // [1]
    float* out = (float*)d_out;

    int B = in_sizes[0] / T_DIM;               // 8192
    agp_kernel<<<B, NTHREADS>>>(H, sw, sb, out, B);
}